// round 1
// baseline (speedup 1.0000x reference)
#include <cuda_runtime.h>
#include <math_constants.h>

#define NMAX 40000
#define EMAX 640000
#define HDIM 128
#define DOUTC 64
#define GMAX 64

// ---------------- static scratch (no allocation allowed) ----------------
__device__ float g_dinv[NMAX];
__device__ int   g_count[NMAX];
__device__ int   g_offs[NMAX + 1];
__device__ int   g_csr[EMAX];
__device__ int   g_bsums[64];
__device__ int   g_start[GMAX + 1];
__device__ float g_bufA[NMAX * HDIM];
__device__ float g_bufB[NMAX * HDIM];
__device__ float g_no[NMAX * DOUTC];

// ---------------- small utility kernels ----------------
__global__ void zero_int_kernel(int* p, int n) {
    int i = blockIdx.x * blockDim.x + threadIdx.x;
    if (i < n) p[i] = 0;
}

__global__ void count_kernel(const int* __restrict__ dst, int E, int* __restrict__ count) {
    int e = blockIdx.x * blockDim.x + threadIdx.x;
    if (e < E) atomicAdd(&count[dst[e]], 1);
}

// Per-block exclusive scan (block = 1024)
__global__ void scan1_kernel(const int* __restrict__ count, int n,
                             int* __restrict__ offs, int* __restrict__ bsums) {
    __shared__ int sm[1024];
    int i = blockIdx.x * 1024 + threadIdx.x;
    int v = (i < n) ? count[i] : 0;
    sm[threadIdx.x] = v;
    __syncthreads();
    for (int off = 1; off < 1024; off <<= 1) {
        int t = (threadIdx.x >= off) ? sm[threadIdx.x - off] : 0;
        __syncthreads();
        sm[threadIdx.x] += t;
        __syncthreads();
    }
    if (i < n) offs[i] = sm[threadIdx.x] - v;     // exclusive within block
    if (threadIdx.x == 1023) bsums[blockIdx.x] = sm[1023];
}

// Exclusive scan of block sums (single block of 64)
__global__ void scan2_kernel(int* bsums, int nb) {
    __shared__ int sm[64];
    int t = threadIdx.x;
    int orig = (t < nb) ? bsums[t] : 0;
    sm[t] = orig;
    __syncthreads();
    for (int off = 1; off < 64; off <<= 1) {
        int v = (t >= off) ? sm[t - off] : 0;
        __syncthreads();
        sm[t] += v;
        __syncthreads();
    }
    if (t < nb) bsums[t] = sm[t] - orig;          // exclusive
}

__global__ void scan3_kernel(int* __restrict__ offs, const int* __restrict__ bsums,
                             int n, int E, const int* __restrict__ count,
                             float* __restrict__ dinv) {
    int i = blockIdx.x * blockDim.x + threadIdx.x;
    if (i < n) {
        offs[i] += bsums[i >> 10];
        dinv[i] = rsqrtf((float)(count[i] + 1));  // +1 self loop, always > 0
    }
    if (i == 0) offs[n] = E;
}

__global__ void scatter_kernel(const int* __restrict__ src, const int* __restrict__ dst,
                               int E, const int* __restrict__ offs,
                               int* __restrict__ cursor, int* __restrict__ csr) {
    int e = blockIdx.x * blockDim.x + threadIdx.x;
    if (e < E) {
        int d = dst[e];
        int p = atomicAdd(&cursor[d], 1);
        csr[offs[d] + p] = src[e];
    }
}

// ---------------- SGEMM: out = A (n x 128) @ W (128 x OUTC) [+ bias] ----------------
// Tile 64 rows x OUTC cols, 256 threads, each thread 4 rows x OUTC/16 cols.
template <int OUTC>
__global__ void gemm_kernel(const float* __restrict__ A, const float* __restrict__ W,
                            const float* __restrict__ bias, float* __restrict__ out, int n) {
    constexpr int CP = OUTC / 16;   // cols per thread (8 or 4)
    extern __shared__ float smem[];
    float* ws = smem;               // [128][OUTC]
    float* xs = smem + 128 * OUTC;  // [64][132] padded

    const int tid = threadIdx.x;
    const int row0 = blockIdx.x * 64;

    for (int i = tid * 4; i < 128 * OUTC; i += 256 * 4)
        *(float4*)(ws + i) = *(const float4*)(W + i);

    for (int i = tid; i < 64 * 32; i += 256) {
        int r = i >> 5, k4 = (i & 31) << 2;
        int gr = row0 + r;
        float4 v = (gr < n) ? *(const float4*)(A + (size_t)gr * 128 + k4)
                            : make_float4(0.f, 0.f, 0.f, 0.f);
        *(float4*)(&xs[r * 132 + k4]) = v;
    }
    __syncthreads();

    const int rg = tid >> 4, cg = tid & 15;
    float acc[4][CP];
#pragma unroll
    for (int i = 0; i < 4; i++)
#pragma unroll
        for (int j = 0; j < CP; j++) acc[i][j] = 0.f;

#pragma unroll 4
    for (int k = 0; k < 128; k++) {
        float xv[4];
#pragma unroll
        for (int i = 0; i < 4; i++) xv[i] = xs[(rg * 4 + i) * 132 + k];
        float wv[CP];
#pragma unroll
        for (int j = 0; j < CP; j += 4)
            *(float4*)(wv + j) = *(float4*)(ws + k * OUTC + cg * CP + j);
#pragma unroll
        for (int i = 0; i < 4; i++)
#pragma unroll
            for (int j = 0; j < CP; j++) acc[i][j] += xv[i] * wv[j];
    }

#pragma unroll
    for (int i = 0; i < 4; i++) {
        int r = row0 + rg * 4 + i;
        if (r < n) {
#pragma unroll
            for (int j = 0; j < CP; j += 4) {
                float4 v;
                v.x = acc[i][j + 0];
                v.y = acc[i][j + 1];
                v.z = acc[i][j + 2];
                v.w = acc[i][j + 3];
                if (bias) {
                    float4 b = *(const float4*)(bias + cg * CP + j);
                    v.x += b.x; v.y += b.y; v.z += b.z; v.w += b.w;
                }
                *(float4*)(out + (size_t)r * OUTC + cg * CP + j) = v;
            }
        }
    }
}

// ---------------- Aggregation (GCN propagate), optional fused relu+LN1+LN2 ----------
__device__ __forceinline__ float warp_sum(float v) {
#pragma unroll
    for (int o = 16; o; o >>= 1) v += __shfl_xor_sync(0xffffffffu, v, o);
    return v;
}

template <bool POST>
__global__ void agg_kernel(const float* __restrict__ t, const float* __restrict__ bias,
                           const float* __restrict__ g1, const float* __restrict__ b1,
                           const float* __restrict__ g2, const float* __restrict__ b2,
                           float* __restrict__ out, int n,
                           const int* __restrict__ offs, const int* __restrict__ csr,
                           const float* __restrict__ dinv) {
    int w = (blockIdx.x * blockDim.x + threadIdx.x) >> 5;
    if (w >= n) return;
    int lane = threadIdx.x & 31;
    int c0 = lane * 4;

    float di = dinv[w];
    float4 sv = *(const float4*)(t + (size_t)w * HDIM + c0);
    float4 acc;
    acc.x = di * sv.x; acc.y = di * sv.y; acc.z = di * sv.z; acc.w = di * sv.w;

    int e = offs[w], end = offs[w + 1];
    for (; e + 4 <= end; e += 4) {
        int s0 = csr[e], s1 = csr[e + 1], s2 = csr[e + 2], s3 = csr[e + 3];
        float d0 = dinv[s0], d1 = dinv[s1], d2 = dinv[s2], d3 = dinv[s3];
        float4 v0 = *(const float4*)(t + (size_t)s0 * HDIM + c0);
        float4 v1 = *(const float4*)(t + (size_t)s1 * HDIM + c0);
        float4 v2 = *(const float4*)(t + (size_t)s2 * HDIM + c0);
        float4 v3 = *(const float4*)(t + (size_t)s3 * HDIM + c0);
        acc.x += d0 * v0.x + d1 * v1.x + d2 * v2.x + d3 * v3.x;
        acc.y += d0 * v0.y + d1 * v1.y + d2 * v2.y + d3 * v3.y;
        acc.z += d0 * v0.z + d1 * v1.z + d2 * v2.z + d3 * v3.z;
        acc.w += d0 * v0.w + d1 * v1.w + d2 * v2.w + d3 * v3.w;
    }
    for (; e < end; e++) {
        int s = csr[e];
        float ds = dinv[s];
        float4 v = *(const float4*)(t + (size_t)s * HDIM + c0);
        acc.x += ds * v.x; acc.y += ds * v.y; acc.z += ds * v.z; acc.w += ds * v.w;
    }

    float4 bv = *(const float4*)(bias + c0);
    float4 h;
    h.x = bv.x + di * acc.x;
    h.y = bv.y + di * acc.y;
    h.z = bv.z + di * acc.z;
    h.w = bv.w + di * acc.w;

    if (POST) {
        // relu
        h.x = fmaxf(h.x, 0.f); h.y = fmaxf(h.y, 0.f);
        h.z = fmaxf(h.z, 0.f); h.w = fmaxf(h.w, 0.f);
        const float inv = 1.f / 128.f, eps = 1e-5f;
        // LN1
        {
            float mu = warp_sum(h.x + h.y + h.z + h.w) * inv;
            float dx = h.x - mu, dy = h.y - mu, dz = h.z - mu, dw = h.w - mu;
            float var = warp_sum(dx * dx + dy * dy + dz * dz + dw * dw) * inv;
            float rs = rsqrtf(var + eps);
            float4 G = *(const float4*)(g1 + c0);
            float4 B = *(const float4*)(b1 + c0);
            h.x = dx * rs * G.x + B.x; h.y = dy * rs * G.y + B.y;
            h.z = dz * rs * G.z + B.z; h.w = dw * rs * G.w + B.w;
        }
        // LN2
        {
            float mu = warp_sum(h.x + h.y + h.z + h.w) * inv;
            float dx = h.x - mu, dy = h.y - mu, dz = h.z - mu, dw = h.w - mu;
            float var = warp_sum(dx * dx + dy * dy + dz * dz + dw * dw) * inv;
            float rs = rsqrtf(var + eps);
            float4 G = *(const float4*)(g2 + c0);
            float4 B = *(const float4*)(b2 + c0);
            h.x = dx * rs * G.x + B.x; h.y = dy * rs * G.y + B.y;
            h.z = dz * rs * G.z + B.z; h.w = dw * rs * G.w + B.w;
        }
    }
    *(float4*)(out + (size_t)w * HDIM + c0) = h;
}

// ---------------- graph boundaries via binary search on sorted batch ----------------
__global__ void bounds_kernel(const int* __restrict__ batch, int n, int* __restrict__ start,
                              int G) {
    int g = threadIdx.x;
    if (g > G) return;
    int lo = 0, hi = n;
    while (lo < hi) {
        int m = (lo + hi) >> 1;
        if (batch[m] < g) lo = m + 1; else hi = m;
    }
    start[g] = lo;
}

// ---------------- fused pooling (max+mean) + log_softmax, one block per graph --------
__global__ void pool_softmax_kernel(const float* __restrict__ no,
                                    const int* __restrict__ start,
                                    float* __restrict__ out) {
    __shared__ float sv[128];
    __shared__ float sred[256];
    __shared__ float wred[8];
    int g = blockIdx.x;
    int beg = start[g], end = start[g + 1];
    int tid = threadIdx.x;
    int c = tid & 63, sub = tid >> 6;

    float mx = -CUDART_INF_F, sm = 0.f;
    for (int i = beg + sub; i < end; i += 4) {
        float v = no[(size_t)i * DOUTC + c];
        mx = fmaxf(mx, v);
        sm += v;
    }
    sred[tid] = mx;
    __syncthreads();
    float m4 = 0.f;
    if (sub == 0)
        m4 = fmaxf(fmaxf(sred[c], sred[c + 64]), fmaxf(sred[c + 128], sred[c + 192]));
    __syncthreads();
    sred[tid] = sm;
    __syncthreads();
    if (sub == 0) {
        float s4 = sred[c] + sred[c + 64] + sred[c + 128] + sred[c + 192];
        float cnt = (float)(end - beg);
        sv[c] = m4;
        sv[64 + c] = s4 / fmaxf(cnt, 1.f);
    }
    __syncthreads();

    float v = (tid < 128) ? sv[tid] : -CUDART_INF_F;
    float m = v;
#pragma unroll
    for (int o = 16; o; o >>= 1) m = fmaxf(m, __shfl_xor_sync(0xffffffffu, m, o));
    if ((tid & 31) == 0) wred[tid >> 5] = m;
    __syncthreads();
    if (tid == 0) {
        float mm = wred[0];
        for (int i = 1; i < 8; i++) mm = fmaxf(mm, wred[i]);
        wred[0] = mm;
    }
    __syncthreads();
    float M = wred[0];
    __syncthreads();
    float e = (tid < 128) ? expf(v - M) : 0.f;
    float s = e;
#pragma unroll
    for (int o = 16; o; o >>= 1) s += __shfl_xor_sync(0xffffffffu, s, o);
    if ((tid & 31) == 0) wred[tid >> 5] = s;
    __syncthreads();
    if (tid == 0) {
        float ss = 0.f;
        for (int i = 0; i < 8; i++) ss += wred[i];
        wred[0] = ss;
    }
    __syncthreads();
    float S = wred[0];
    if (tid < 128) out[g * 128 + tid] = v - M - logf(S);
}

// ---------------- host orchestration ----------------
extern "C" void kernel_launch(void* const* d_in, const int* in_sizes, int n_in,
                              void* d_out, int out_size) {
    const float* x   = (const float*)d_in[0];
    const int*   ei  = (const int*)d_in[1];
    const int*   bat = (const int*)d_in[2];
    const float* W1  = (const float*)d_in[3];
    const float* b1  = (const float*)d_in[4];
    const float* ln1g = (const float*)d_in[5];
    const float* ln1b = (const float*)d_in[6];
    const float* ln2g = (const float*)d_in[7];
    const float* ln2b = (const float*)d_in[8];
    const float* W2  = (const float*)d_in[9];
    const float* b2  = (const float*)d_in[10];
    const float* W3  = (const float*)d_in[11];
    const float* b3  = (const float*)d_in[12];
    const float* Wp1 = (const float*)d_in[13];
    const float* bp1 = (const float*)d_in[14];
    const float* Wp2 = (const float*)d_in[15];
    const float* bp2 = (const float*)d_in[16];
    float* out = (float*)d_out;

    const int N = in_sizes[0] / HDIM;
    const int E = in_sizes[1] / 2;
    const int G = out_size / (2 * DOUTC);
    const int* src = ei;
    const int* dst = ei + E;

    // device symbol addresses
    float *dinv, *bufA, *bufB, *no;
    int *count, *offs, *csr, *bsums, *start;
    cudaGetSymbolAddress((void**)&dinv,  g_dinv);
    cudaGetSymbolAddress((void**)&count, g_count);
    cudaGetSymbolAddress((void**)&offs,  g_offs);
    cudaGetSymbolAddress((void**)&csr,   g_csr);
    cudaGetSymbolAddress((void**)&bsums, g_bsums);
    cudaGetSymbolAddress((void**)&start, g_start);
    cudaGetSymbolAddress((void**)&bufA,  g_bufA);
    cudaGetSymbolAddress((void**)&bufB,  g_bufB);
    cudaGetSymbolAddress((void**)&no,    g_no);

    static bool attr_set = false;
    if (!attr_set) {
        cudaFuncSetAttribute(gemm_kernel<128>, cudaFuncAttributeMaxDynamicSharedMemorySize,
                             (128 * 128 + 64 * 132) * 4);
        cudaFuncSetAttribute(gemm_kernel<64>, cudaFuncAttributeMaxDynamicSharedMemorySize,
                             (128 * 64 + 64 * 132) * 4);
        attr_set = true;
    }

    const int nb1024 = (N + 1023) / 1024;

    // ---- CSR build + dinv ----
    zero_int_kernel<<<(N + 255) / 256, 256>>>(count, N);
    count_kernel<<<(E + 255) / 256, 256>>>(dst, E, count);
    scan1_kernel<<<nb1024, 1024>>>(count, N, offs, bsums);
    scan2_kernel<<<1, 64>>>(bsums, nb1024);
    scan3_kernel<<<(N + 255) / 256, 256>>>(offs, bsums, N, E, count, dinv);
    zero_int_kernel<<<(N + 255) / 256, 256>>>(count, N);
    scatter_kernel<<<(E + 255) / 256, 256>>>(src, dst, E, offs, count, csr);

    const int gemmBlocks = (N + 63) / 64;
    const int gemmSmem128 = (128 * 128 + 64 * 132) * 4;
    const int gemmSmem64  = (128 * 64 + 64 * 132) * 4;
    const int aggBlocks = (N * 32 + 255) / 256;

    // layer 1: gemm + aggregate + relu + ln1 + ln2
    gemm_kernel<128><<<gemmBlocks, 256, gemmSmem128>>>(x, W1, nullptr, bufA, N);
    agg_kernel<true><<<aggBlocks, 256>>>(bufA, b1, ln1g, ln1b, ln2g, ln2b,
                                         bufB, N, offs, csr, dinv);
    // layer 2
    gemm_kernel<128><<<gemmBlocks, 256, gemmSmem128>>>(bufB, W2, nullptr, bufA, N);
    agg_kernel<false><<<aggBlocks, 256>>>(bufA, b2, nullptr, nullptr, nullptr, nullptr,
                                          bufB, N, offs, csr, dinv);
    // layer 3
    gemm_kernel<128><<<gemmBlocks, 256, gemmSmem128>>>(bufB, W3, nullptr, bufA, N);
    agg_kernel<false><<<aggBlocks, 256>>>(bufA, b3, nullptr, nullptr, nullptr, nullptr,
                                          bufB, N, offs, csr, dinv);
    // MLP
    gemm_kernel<128><<<gemmBlocks, 256, gemmSmem128>>>(bufB, Wp1, bp1, bufA, N);
    gemm_kernel<64><<<gemmBlocks, 256, gemmSmem64>>>(bufA, Wp2, bp2, no, N);

    // pooling + log_softmax
    bounds_kernel<<<1, 128>>>(bat, N, start, G);
    pool_softmax_kernel<<<G, 256>>>(no, start, out);
}